// round 17
// baseline (speedup 1.0000x reference)
#include <cuda_runtime.h>
#include <cstdint>

// FrozenBNBEmbedding: out[r, :] = code[ weight[token_r, :] ] * absmax[token_r]
// BLOCK (4096) == DIM (4096) -> per-row scalar scale absmax[token].
//
// Inputs (metadata order):
//   d_in[0] = input  : int32 [4, 2048]           token ids (8192)
//   d_in[1] = weight : int32 [50400, 4096]       int8 codes stored as int32
//   d_in[2] = absmax : float32 [50400]           per-block (== per-row) scale
//   d_in[3] = code   : float32 [256]             dequant LUT
// Output: float32 [4, 2048, 4096]
//
// R16: persistent grid-stride CTAs + software-pipelined row loop (8 LDG.128
// in flight per warp at all times) + 32x bank-replicated LUT (conflict-free
// LDS) + streaming stores.

#define DIM 4096
#define NCHUNK (DIM / 4 / 256)   // 4 int4 chunks per thread at 256 threads
#define GRID_CTAS 608            // 152 SMs * 4 resident CTAs

__global__ __launch_bounds__(256, 4)
void bnb_embed_kernel(const int* __restrict__ tokens,
                      const int* __restrict__ weight,
                      const float* __restrict__ absmax,
                      const float* __restrict__ code,
                      float* __restrict__ out,
                      int n_rows)
{
    // 32 interleaved copies of the 256-entry LUT: lut[idx*32 + lane].
    // Bank of lut[idx*32+lane] == lane  ->  conflict-free for any idx pattern.
    __shared__ float lut[256 * 32];

    const int tid  = threadIdx.x;
    const int lane = tid & 31;

    #pragma unroll
    for (int j = tid; j < 256 * 32; j += 256)
        lut[j] = __ldg(&code[j >> 5]);   // consecutive j -> consecutive banks
    __syncthreads();

    const int stride = gridDim.x;
    int row = blockIdx.x;
    if (row >= n_rows) return;

    // ---- prologue: issue row 0's loads ----
    int   token = __ldg(&tokens[row]);
    float scale = __ldg(&absmax[token]);
    const int4* wrow = reinterpret_cast<const int4*>(weight) + (size_t)token * (DIM / 4);
    int4 q0 = __ldg(&wrow[tid + 0 * 256]);
    int4 q1 = __ldg(&wrow[tid + 1 * 256]);
    int4 q2 = __ldg(&wrow[tid + 2 * 256]);
    int4 q3 = __ldg(&wrow[tid + 3 * 256]);

    while (true) {
        // ---- prefetch next row's loads BEFORE consuming current row ----
        const int nrow = row + stride;
        const bool has_next = (nrow < n_rows);
        int4 p0, p1, p2, p3;
        float nscale = 0.0f;
        if (has_next) {
            const int ntok = __ldg(&tokens[nrow]);
            nscale = __ldg(&absmax[ntok]);
            const int4* nw = reinterpret_cast<const int4*>(weight) + (size_t)ntok * (DIM / 4);
            p0 = __ldg(&nw[tid + 0 * 256]);
            p1 = __ldg(&nw[tid + 1 * 256]);
            p2 = __ldg(&nw[tid + 2 * 256]);
            p3 = __ldg(&nw[tid + 3 * 256]);
        }

        // ---- dequant + store current row ----
        float4* orow = reinterpret_cast<float4*>(out) + (size_t)row * (DIM / 4);
        float4 v;

        v.x = lut[(q0.x << 5) | lane] * scale;
        v.y = lut[(q0.y << 5) | lane] * scale;
        v.z = lut[(q0.z << 5) | lane] * scale;
        v.w = lut[(q0.w << 5) | lane] * scale;
        __stcs(&orow[tid + 0 * 256], v);

        v.x = lut[(q1.x << 5) | lane] * scale;
        v.y = lut[(q1.y << 5) | lane] * scale;
        v.z = lut[(q1.z << 5) | lane] * scale;
        v.w = lut[(q1.w << 5) | lane] * scale;
        __stcs(&orow[tid + 1 * 256], v);

        v.x = lut[(q2.x << 5) | lane] * scale;
        v.y = lut[(q2.y << 5) | lane] * scale;
        v.z = lut[(q2.z << 5) | lane] * scale;
        v.w = lut[(q2.w << 5) | lane] * scale;
        __stcs(&orow[tid + 2 * 256], v);

        v.x = lut[(q3.x << 5) | lane] * scale;
        v.y = lut[(q3.y << 5) | lane] * scale;
        v.z = lut[(q3.z << 5) | lane] * scale;
        v.w = lut[(q3.w << 5) | lane] * scale;
        __stcs(&orow[tid + 3 * 256], v);

        if (!has_next) break;
        q0 = p0; q1 = p1; q2 = p2; q3 = p3;
        scale = nscale;
        row = nrow;
    }
}

extern "C" void kernel_launch(void* const* d_in, const int* in_sizes, int n_in,
                              void* d_out, int out_size)
{
    const int*   tokens = (const int*)d_in[0];
    const int*   weight = (const int*)d_in[1];
    const float* absmax = (const float*)d_in[2];
    const float* code   = (const float*)d_in[3];
    float*       out    = (float*)d_out;

    const int n_rows = in_sizes[0];   // 8192 tokens = output rows
    const int grid   = (n_rows < GRID_CTAS) ? n_rows : GRID_CTAS;

    bnb_embed_kernel<<<grid, 256>>>(tokens, weight, absmax, code, out, n_rows);
}